// round 2
// baseline (speedup 1.0000x reference)
#include <cuda_runtime.h>
#include <cstdint>

// ---------------------------------------------------------------------------
// out[n,o] = sum_s attn[s] * (X[s] @ W[s])[n,o] + bias[o]
// One GEMM: A[m,k] = X[k/128][m][k%128] (M=200000, K=1024),
//           Bt[o,k] = attn[s]*W[s][i][o] (N=128), tf32 via mma.sync (sm_103-safe).
// ---------------------------------------------------------------------------

#define NROWS    200000
#define KTOT     1024
#define BLOCK_M  256
#define NSTAGES  4

#define A_BYTES      (BLOCK_M * 128)        // 256 rows x 32 tf32 (128B)
#define B_BYTES      (128 * 128)            // 128 rows x 32 tf32
#define STAGE_BYTES  (A_BYTES + B_BYTES)    // 49152

#define SMEM_BIAS    0                      // 128 floats
#define SMEM_STAGE0  1024
#define SMEM_TOTAL   (SMEM_STAGE0 + NSTAGES * STAGE_BYTES)   // 197632

// B transposed + attn-folded + tf32(RN): g_Wt[o][k], 512 KB (L2-resident).
__device__ float g_Wt[128 * KTOT];

// ---- helpers ---------------------------------------------------------------

__device__ __forceinline__ uint32_t smem_u32(const void* p) {
    uint32_t a;
    asm("{ .reg .u64 t; cvta.to.shared.u64 t, %1; cvt.u32.u64 %0, t; }"
        : "=r"(a) : "l"(p));
    return a;
}

__device__ __forceinline__ void cp16(uint32_t saddr, const void* gaddr, int src_size) {
    asm volatile("cp.async.cg.shared.global [%0], [%1], 16, %2;"
                 :: "r"(saddr), "l"(gaddr), "r"(src_size));
}

__device__ __forceinline__ void ldsm_x4(uint32_t* r, uint32_t addr) {
    asm volatile("ldmatrix.sync.aligned.m8n8.x4.shared.b16 {%0,%1,%2,%3}, [%4];"
                 : "=r"(r[0]), "=r"(r[1]), "=r"(r[2]), "=r"(r[3]) : "r"(addr));
}

__device__ __forceinline__ void mma_tf32(float* c, const uint32_t* a,
                                         uint32_t b0, uint32_t b1) {
    asm volatile(
        "mma.sync.aligned.m16n8k8.row.col.f32.tf32.tf32.f32 "
        "{%0,%1,%2,%3}, {%4,%5,%6,%7}, {%8,%9}, {%0,%1,%2,%3};"
        : "+f"(c[0]), "+f"(c[1]), "+f"(c[2]), "+f"(c[3])
        : "r"(a[0]), "r"(a[1]), "r"(a[2]), "r"(a[3]), "r"(b0), "r"(b1));
}

// Issue cp.asyncs for K-chunk t (32 floats) into ring slot. 512 threads.
__device__ __forceinline__ void issue_stage(const float* __restrict__ X,
                                            uint32_t smem_base, int slot, int t,
                                            int m0, int tid) {
    const int s  = t >> 2;             // support matrix index
    const int i0 = (t & 3) << 5;       // 32-float chunk within IN_F=128
    const uint32_t aBase = smem_base + SMEM_STAGE0 + slot * STAGE_BYTES;
    const uint32_t bBase = aBase + A_BYTES;
    const float* gA = X + ((size_t)s * NROWS + m0) * 128 + i0;

    // A: 256 rows x 8 x 16B (XOR-8 swizzle)
    #pragma unroll
    for (int it = 0; it < 4; it++) {
        int q = tid + it * 512;
        int r = q >> 3, c = q & 7;
        uint32_t sa = aBase + (uint32_t)(r * 128 + ((c ^ (r & 7)) << 4));
        const float* ga = gA + (size_t)r * 128 + (c << 2);
        int ok = ((m0 + r) < NROWS) ? 16 : 0;
        cp16(sa, ga, ok);
    }
    // B: 128 rows x 8 x 16B
    #pragma unroll
    for (int it = 0; it < 2; it++) {
        int q = tid + it * 512;
        int r = q >> 3, c = q & 7;
        uint32_t sb = bBase + (uint32_t)(r * 128 + ((c ^ (r & 7)) << 4));
        const float* gb = g_Wt + (size_t)r * KTOT + (t << 5) + (c << 2);
        cp16(sb, gb, 16);
    }
}

// ---- prep: g_Wt[o][k] = rn_tf32( attn[s] * W[s][i][o] * comp ) --------------

__global__ void prep_kernel(const float* __restrict__ W, const float* __restrict__ attn) {
    int idx = blockIdx.x * 256 + threadIdx.x;
    if (idx >= 128 * KTOT) return;
    int o = idx >> 10;
    int k = idx & (KTOT - 1);
    int s = k >> 7;
    int i = k & 127;
    // 1.0001692 cancels the mean downward bias from HW truncation of the
    // raw-fp32 A operand to tf32 inside HMMA (E[rel loss] = 2^-12 * ln2 * 2).
    float v = attn[s] * W[((s << 7) + i) * 128 + o] * 1.0001692f;
    uint32_t b;
    asm("cvt.rn.tf32.f32 %0, %1;" : "=r"(b) : "f"(v));
    g_Wt[idx] = __uint_as_float(b);
}

// ---- main GEMM --------------------------------------------------------------

__global__ void __launch_bounds__(512, 1)
mgc_kernel(const float* __restrict__ X, const float* __restrict__ bias,
           float* __restrict__ out) {
    extern __shared__ char smem[];
    const uint32_t sb  = smem_u32(smem);
    const int tid = threadIdx.x;
    const int lid = tid & 31;
    const int wid = tid >> 5;
    const int wm  = wid >> 1;          // 0..7  (32-row slices)
    const int wn  = wid & 1;           // 0..1  (64-col slices)
    const int m0  = blockIdx.x * BLOCK_M;

    if (tid < 128)
        reinterpret_cast<float*>(smem)[tid] = bias[tid];

    // per-thread ldmatrix row bases
    const int arow = wm * 32 + (lid & 15);     // A: rows arow, arow+16
    const int brow = wn * 64 + (lid & 7);      // B: rows brow + nt*8
    const int asel = lid >> 4;                 // A chunk selector (0/1)
    const int bsel = lid >> 3;                 // B chunk selector (0..3)

    float acc[2][8][4];
    #pragma unroll
    for (int mt = 0; mt < 2; mt++)
        #pragma unroll
        for (int nt = 0; nt < 8; nt++)
            #pragma unroll
            for (int v = 0; v < 4; v++) acc[mt][nt][v] = 0.f;

    // prologue: fill ring
    #pragma unroll
    for (int p = 0; p < NSTAGES; p++) {
        issue_stage(X, sb, p, p, m0, tid);
        asm volatile("cp.async.commit_group;" ::: "memory");
    }

    const int NITER = KTOT / 32;   // 32
    for (int t = 0; t < NITER; t++) {
        const int slot = t & (NSTAGES - 1);
        asm volatile("cp.async.wait_group %0;" :: "n"(NSTAGES - 1) : "memory");
        __syncthreads();

        const uint32_t aB = sb + SMEM_STAGE0 + slot * STAGE_BYTES;
        const uint32_t bB = aB + A_BYTES;

        #pragma unroll
        for (int jj = 0; jj < 4; jj += 2) {      // two k8-steps per pass
            uint32_t bf[8][4];
            #pragma unroll
            for (int nt = 0; nt < 8; nt++) {
                int n = brow + nt * 8;
                uint32_t addr = bB + (uint32_t)(n * 128 +
                                  ((((jj << 1) + bsel) ^ (n & 7)) << 4));
                ldsm_x4(bf[nt], addr);
            }
            #pragma unroll
            for (int dj = 0; dj < 2; dj++) {
                const int j = jj + dj;
                uint32_t af[2][4];
                #pragma unroll
                for (int mt = 0; mt < 2; mt++) {
                    int r = arow + mt * 16;
                    uint32_t addr = aB + (uint32_t)(r * 128 +
                                      ((((j << 1) + asel) ^ (r & 7)) << 4));
                    ldsm_x4(af[mt], addr);
                }
                #pragma unroll
                for (int mt = 0; mt < 2; mt++)
                    #pragma unroll
                    for (int nt = 0; nt < 8; nt++)
                        mma_tf32(acc[mt][nt], af[mt], bf[nt][2 * dj], bf[nt][2 * dj + 1]);
            }
        }

        __syncthreads();
        if (t + NSTAGES < NITER)
            issue_stage(X, sb, slot, t + NSTAGES, m0, tid);
        asm volatile("cp.async.commit_group;" ::: "memory");
    }

    // ---- epilogue: acc + bias -> out ----------------------------------------
    const float* bs = reinterpret_cast<const float*>(smem);
    const int tig = lid & 3;
    const int g   = lid >> 2;

    float2 bv[8];
    #pragma unroll
    for (int nt = 0; nt < 8; nt++) {
        int c = wn * 64 + nt * 8 + 2 * tig;
        bv[nt].x = bs[c];
        bv[nt].y = bs[c + 1];
    }

    #pragma unroll
    for (int mt = 0; mt < 2; mt++) {
        int mrow = m0 + wm * 32 + mt * 16 + g;
        #pragma unroll
        for (int half = 0; half < 2; half++) {       // rows g and g+8
            int m = mrow + half * 8;
            if (m < NROWS) {
                float* po = out + (size_t)m * 128 + wn * 64;
                #pragma unroll
                for (int nt = 0; nt < 8; nt++) {
                    float2 v;
                    v.x = acc[mt][nt][2 * half + 0] + bv[nt].x;
                    v.y = acc[mt][nt][2 * half + 1] + bv[nt].y;
                    *reinterpret_cast<float2*>(po + nt * 8 + 2 * tig) = v;
                }
            }
        }
    }
}

// ---- launch -----------------------------------------------------------------

extern "C" void kernel_launch(void* const* d_in, const int* in_sizes, int n_in,
                              void* d_out, int out_size) {
    const float* X    = (const float*)d_in[0];   // (8, 200000, 128) f32
    const float* W    = (const float*)d_in[1];   // (8, 128, 128)    f32
    const float* attn = (const float*)d_in[2];   // (8,)             f32
    const float* bias = (const float*)d_in[3];   // (128,)           f32
    float* out = (float*)d_out;                  // (200000, 128)    f32

    cudaFuncSetAttribute(mgc_kernel, cudaFuncAttributeMaxDynamicSharedMemorySize,
                         SMEM_TOTAL);

    prep_kernel<<<(128 * KTOT + 255) / 256, 256>>>(W, attn);

    int grid = (NROWS + BLOCK_M - 1) / BLOCK_M;   // 782
    mgc_kernel<<<grid, 512, SMEM_TOTAL>>>(X, bias, out);
}

// round 3
// speedup vs baseline: 1.2701x; 1.2701x over previous
#include <cuda_runtime.h>
#include <cstdint>

// ---------------------------------------------------------------------------
// out[n,o] = sum_s attn[s] * (X[s] @ W[s])[n,o] + bias[o]
// One GEMM: A[m,k] = X[k/128][m][k%128] (M=200000, K=1024),
//           Bt[o,k] = attn[s]*W[s][i][o] (N=128), tf32 via mma.sync.
// R3: BLOCK_M=128 / 256 threads / 3-stage ring -> 2 CTAs/SM (barrier overlap).
// ---------------------------------------------------------------------------

#define NROWS    200000
#define KTOT     1024
#define BLOCK_M  128
#define NSTAGES  3

#define A_BYTES      (BLOCK_M * 128)        // 128 rows x 32 tf32 (128B)
#define B_BYTES      (128 * 128)
#define STAGE_BYTES  (A_BYTES + B_BYTES)    // 32768

#define SMEM_BIAS    0
#define SMEM_STAGE0  1024
#define SMEM_TOTAL   (SMEM_STAGE0 + NSTAGES * STAGE_BYTES)   // 99328 -> 2 CTAs/SM

// B transposed + attn-folded + tf32(RN): g_Wt[o][k], 512 KB (L2-resident).
__device__ float g_Wt[128 * KTOT];

// ---- helpers ---------------------------------------------------------------

__device__ __forceinline__ uint32_t smem_u32(const void* p) {
    uint32_t a;
    asm("{ .reg .u64 t; cvta.to.shared.u64 t, %1; cvt.u32.u64 %0, t; }"
        : "=r"(a) : "l"(p));
    return a;
}

__device__ __forceinline__ void cp16(uint32_t saddr, const void* gaddr, int src_size) {
    asm volatile("cp.async.cg.shared.global [%0], [%1], 16, %2;"
                 :: "r"(saddr), "l"(gaddr), "r"(src_size));
}

__device__ __forceinline__ void ldsm_x4(uint32_t* r, uint32_t addr) {
    asm volatile("ldmatrix.sync.aligned.m8n8.x4.shared.b16 {%0,%1,%2,%3}, [%4];"
                 : "=r"(r[0]), "=r"(r[1]), "=r"(r[2]), "=r"(r[3]) : "r"(addr));
}

__device__ __forceinline__ void mma_tf32(float* c, const uint32_t* a,
                                         uint32_t b0, uint32_t b1) {
    asm volatile(
        "mma.sync.aligned.m16n8k8.row.col.f32.tf32.tf32.f32 "
        "{%0,%1,%2,%3}, {%4,%5,%6,%7}, {%8,%9}, {%0,%1,%2,%3};"
        : "+f"(c[0]), "+f"(c[1]), "+f"(c[2]), "+f"(c[3])
        : "r"(a[0]), "r"(a[1]), "r"(a[2]), "r"(a[3]), "r"(b0), "r"(b1));
}

// Issue cp.asyncs for K-chunk t (32 floats) into ring slot. 256 threads.
__device__ __forceinline__ void issue_stage(const float* __restrict__ X,
                                            uint32_t smem_base, int slot, int t,
                                            int m0, int tid) {
    const int s  = t >> 2;             // support matrix index
    const int i0 = (t & 3) << 5;       // 32-float chunk within IN_F=128
    const uint32_t aBase = smem_base + SMEM_STAGE0 + slot * STAGE_BYTES;
    const uint32_t bBase = aBase + A_BYTES;
    const float* gA = X + ((size_t)s * NROWS + m0) * 128 + i0;

    // A: 128 rows x 8 x 16B (XOR-8 swizzle)
    #pragma unroll
    for (int it = 0; it < 4; it++) {
        int q = tid + it * 256;
        int r = q >> 3, c = q & 7;
        uint32_t sa = aBase + (uint32_t)(r * 128 + ((c ^ (r & 7)) << 4));
        const float* ga = gA + (size_t)r * 128 + (c << 2);
        int ok = ((m0 + r) < NROWS) ? 16 : 0;
        cp16(sa, ga, ok);
    }
    // B: 128 rows x 8 x 16B
    #pragma unroll
    for (int it = 0; it < 4; it++) {
        int q = tid + it * 256;
        int r = q >> 3, c = q & 7;
        uint32_t sb = bBase + (uint32_t)(r * 128 + ((c ^ (r & 7)) << 4));
        const float* gb = g_Wt + (size_t)r * KTOT + (t << 5) + (c << 2);
        cp16(sb, gb, 16);
    }
}

// ---- prep: g_Wt[o][k] = rn_tf32( attn[s] * W[s][i][o] * comp ) --------------

__global__ void prep_kernel(const float* __restrict__ W, const float* __restrict__ attn) {
    int idx = blockIdx.x * 256 + threadIdx.x;
    if (idx >= 128 * KTOT) return;
    int o = idx >> 10;
    int k = idx & (KTOT - 1);
    int s = k >> 7;
    int i = k & 127;
    // 1.0001692 cancels the mean downward bias from HW truncation of the
    // raw-fp32 A operand to tf32 inside HMMA.
    float v = attn[s] * W[((s << 7) + i) * 128 + o] * 1.0001692f;
    uint32_t b;
    asm("cvt.rn.tf32.f32 %0, %1;" : "=r"(b) : "f"(v));
    g_Wt[idx] = __uint_as_float(b);
}

// ---- main GEMM --------------------------------------------------------------

__global__ void __launch_bounds__(256, 2)
mgc_kernel(const float* __restrict__ X, const float* __restrict__ bias,
           float* __restrict__ out) {
    extern __shared__ char smem[];
    const uint32_t sb  = smem_u32(smem);
    const int tid = threadIdx.x;
    const int lid = tid & 31;
    const int wid = tid >> 5;
    const int wm  = wid >> 1;          // 0..3  (32-row slices)
    const int wn  = wid & 1;           // 0..1  (64-col slices)
    const int m0  = blockIdx.x * BLOCK_M;

    if (tid < 128)
        reinterpret_cast<float*>(smem)[tid] = bias[tid];

    // per-thread ldmatrix row bases
    const int arow = wm * 32 + (lid & 15);     // A: rows arow, arow+16
    const int brow = wn * 64 + (lid & 7);      // B: rows brow + nt*8
    const int asel = lid >> 4;                 // A chunk selector (0/1)
    const int bsel = lid >> 3;                 // B chunk selector (0..3)

    float acc[2][8][4];
    #pragma unroll
    for (int mt = 0; mt < 2; mt++)
        #pragma unroll
        for (int nt = 0; nt < 8; nt++)
            #pragma unroll
            for (int v = 0; v < 4; v++) acc[mt][nt][v] = 0.f;

    // prologue: fill ring
    #pragma unroll
    for (int p = 0; p < NSTAGES; p++) {
        issue_stage(X, sb, p, p, m0, tid);
        asm volatile("cp.async.commit_group;" ::: "memory");
    }

    const int NITER = KTOT / 32;   // 32
    for (int t = 0; t < NITER; t++) {
        const int slot = (t % NSTAGES);
        asm volatile("cp.async.wait_group %0;" :: "n"(NSTAGES - 1) : "memory");
        __syncthreads();

        const uint32_t aB = sb + SMEM_STAGE0 + slot * STAGE_BYTES;
        const uint32_t bB = aB + A_BYTES;

        #pragma unroll
        for (int jj = 0; jj < 4; jj += 2) {      // two k8-steps per pass
            uint32_t bf[8][4];
            #pragma unroll
            for (int nt = 0; nt < 8; nt++) {
                int n = brow + nt * 8;
                uint32_t addr = bB + (uint32_t)(n * 128 +
                                  ((((jj << 1) + bsel) ^ (n & 7)) << 4));
                ldsm_x4(bf[nt], addr);
            }
            #pragma unroll
            for (int dj = 0; dj < 2; dj++) {
                const int j = jj + dj;
                uint32_t af[2][4];
                #pragma unroll
                for (int mt = 0; mt < 2; mt++) {
                    int r = arow + mt * 16;
                    uint32_t addr = aB + (uint32_t)(r * 128 +
                                      ((((j << 1) + asel) ^ (r & 7)) << 4));
                    ldsm_x4(af[mt], addr);
                }
                #pragma unroll
                for (int mt = 0; mt < 2; mt++)
                    #pragma unroll
                    for (int nt = 0; nt < 8; nt++)
                        mma_tf32(acc[mt][nt], af[mt], bf[nt][2 * dj], bf[nt][2 * dj + 1]);
            }
        }

        __syncthreads();
        if (t + NSTAGES < NITER)
            issue_stage(X, sb, slot, t + NSTAGES, m0, tid);
        asm volatile("cp.async.commit_group;" ::: "memory");
    }

    // ---- epilogue: acc + bias -> out ----------------------------------------
    const float* bs = reinterpret_cast<const float*>(smem);
    const int tig = lid & 3;
    const int g   = lid >> 2;

    float2 bv[8];
    #pragma unroll
    for (int nt = 0; nt < 8; nt++) {
        int c = wn * 64 + nt * 8 + 2 * tig;
        bv[nt].x = bs[c];
        bv[nt].y = bs[c + 1];
    }

    #pragma unroll
    for (int mt = 0; mt < 2; mt++) {
        int mrow = m0 + wm * 32 + mt * 16 + g;
        #pragma unroll
        for (int half = 0; half < 2; half++) {       // rows g and g+8
            int m = mrow + half * 8;
            if (m < NROWS) {
                float* po = out + (size_t)m * 128 + wn * 64;
                #pragma unroll
                for (int nt = 0; nt < 8; nt++) {
                    float2 v;
                    v.x = acc[mt][nt][2 * half + 0] + bv[nt].x;
                    v.y = acc[mt][nt][2 * half + 1] + bv[nt].y;
                    *reinterpret_cast<float2*>(po + nt * 8 + 2 * tig) = v;
                }
            }
        }
    }
}

// ---- launch -----------------------------------------------------------------

extern "C" void kernel_launch(void* const* d_in, const int* in_sizes, int n_in,
                              void* d_out, int out_size) {
    const float* X    = (const float*)d_in[0];   // (8, 200000, 128) f32
    const float* W    = (const float*)d_in[1];   // (8, 128, 128)    f32
    const float* attn = (const float*)d_in[2];   // (8,)             f32
    const float* bias = (const float*)d_in[3];   // (128,)           f32
    float* out = (float*)d_out;                  // (200000, 128)    f32

    cudaFuncSetAttribute(mgc_kernel, cudaFuncAttributeMaxDynamicSharedMemorySize,
                         SMEM_TOTAL);

    prep_kernel<<<(128 * KTOT + 255) / 256, 256>>>(W, attn);

    int grid = (NROWS + BLOCK_M - 1) / BLOCK_M;   // 1563
    mgc_kernel<<<grid, 256, SMEM_TOTAL>>>(X, bias, out);
}

// round 4
// speedup vs baseline: 1.6587x; 1.3060x over previous
#include <cuda_runtime.h>
#include <cuda_fp16.h>
#include <cstdint>

// ---------------------------------------------------------------------------
// out[n,o] = sum_s attn[s] * (X[s] @ W[s])[n,o] + bias[o]
// One GEMM: A[m,k] = X[k/128][m][k%128] (M=200000, K=1024),
//           Bh[o,k] = fp16(attn[s]*W[s][i][o]) (N=128).
// R4: fp16 mma.m16n8k16 (same 10-bit mantissa as tf32, half the tensor cycles).
//     A kept fp32 in smem; converted to fp16 fragments in registers.
// ---------------------------------------------------------------------------

#define NROWS    200000
#define KTOT     1024
#define BLOCK_M  128
#define NSTAGES  4

#define A_BYTES      (BLOCK_M * 128)        // 128 rows x 32 f32
#define B_BYTES      (128 * 64)             // 128 rows x 32 f16
#define STAGE_BYTES  (A_BYTES + B_BYTES)    // 24576

#define SMEM_STAGE0  1024
#define SMEM_TOTAL   (SMEM_STAGE0 + NSTAGES * STAGE_BYTES)   // 99328 -> 2 CTAs/SM

// B transposed + attn-folded, fp16 RN: g_Wh[o][k], 256 KB (L2-resident).
__device__ __half g_Wh[128 * KTOT];

// ---- helpers ---------------------------------------------------------------

__device__ __forceinline__ uint32_t smem_u32(const void* p) {
    uint32_t a;
    asm("{ .reg .u64 t; cvta.to.shared.u64 t, %1; cvt.u32.u64 %0, t; }"
        : "=r"(a) : "l"(p));
    return a;
}

__device__ __forceinline__ void cp16(uint32_t saddr, const void* gaddr, int src_size) {
    asm volatile("cp.async.cg.shared.global [%0], [%1], 16, %2;"
                 :: "r"(saddr), "l"(gaddr), "r"(src_size));
}

__device__ __forceinline__ void ldsm_x2(uint32_t* r, uint32_t addr) {
    asm volatile("ldmatrix.sync.aligned.m8n8.x2.shared.b16 {%0,%1}, [%2];"
                 : "=r"(r[0]), "=r"(r[1]) : "r"(addr));
}

__device__ __forceinline__ void mma_f16(float* c, const uint32_t* a,
                                        uint32_t b0, uint32_t b1) {
    asm volatile(
        "mma.sync.aligned.m16n8k16.row.col.f32.f16.f16.f32 "
        "{%0,%1,%2,%3}, {%4,%5,%6,%7}, {%8,%9}, {%0,%1,%2,%3};"
        : "+f"(c[0]), "+f"(c[1]), "+f"(c[2]), "+f"(c[3])
        : "r"(a[0]), "r"(a[1]), "r"(a[2]), "r"(a[3]), "r"(b0), "r"(b1));
}

// load 2 consecutive f32 at (row w, col base cl) from swizzled A tile,
// convert to packed f16x2 {lo=x[cl], hi=x[cl+1]}
__device__ __forceinline__ uint32_t a_pair_f16(uint32_t aB, int w, int cl) {
    uint32_t addr = aB + (uint32_t)(w * 128 + ((((cl >> 2) ^ (w & 7)) << 4) + (cl & 3) * 4));
    float x, y;
    asm("ld.shared.v2.f32 {%0,%1}, [%2];" : "=f"(x), "=f"(y) : "r"(addr));
    uint32_t d;
    asm("cvt.rn.f16x2.f32 %0, %1, %2;" : "=r"(d) : "f"(y), "f"(x));
    return d;
}

// Issue cp.asyncs for K-chunk t (32 k) into ring slot. 256 threads.
__device__ __forceinline__ void issue_stage(const float* __restrict__ X,
                                            uint32_t smem_base, int slot, int t,
                                            int m0, int tid) {
    const int s  = t >> 2;             // support matrix index
    const int i0 = (t & 3) << 5;       // 32-float chunk within IN_F=128
    const uint32_t aBase = smem_base + SMEM_STAGE0 + slot * STAGE_BYTES;
    const uint32_t bBase = aBase + A_BYTES;
    const float* gA = X + ((size_t)s * NROWS + m0) * 128 + i0;

    // A: 128 rows x 8 x 16B f32 (XOR-8 swizzle on 16B chunks)
    #pragma unroll
    for (int it = 0; it < 4; it++) {
        int q = tid + it * 256;
        int r = q >> 3, c = q & 7;
        uint32_t sa = aBase + (uint32_t)(r * 128 + ((c ^ (r & 7)) << 4));
        const float* ga = gA + (size_t)r * 128 + (c << 2);
        int ok = ((m0 + r) < NROWS) ? 16 : 0;
        cp16(sa, ga, ok);
    }
    // B: 128 rows x 4 x 16B f16 (chunk ^= (row>>1)&3 swizzle)
    #pragma unroll
    for (int it = 0; it < 2; it++) {
        int q = tid + it * 256;
        int r = q >> 2, c = q & 3;
        uint32_t sbb = bBase + (uint32_t)(r * 64 + ((c ^ ((r >> 1) & 3)) << 4));
        const __half* gb = g_Wh + (size_t)r * KTOT + (t << 5) + (c << 3);
        cp16(sbb, gb, 16);
    }
}

// ---- prep: g_Wh[o][k] = fp16_rn( attn[s] * W[s][i][o] ) ---------------------

__global__ void prep_kernel(const float* __restrict__ W, const float* __restrict__ attn) {
    int idx = blockIdx.x * 256 + threadIdx.x;
    if (idx >= 128 * KTOT) return;
    int o = idx >> 10;
    int k = idx & (KTOT - 1);
    int s = k >> 7;
    int i = k & 127;
    float v = attn[s] * W[((s << 7) + i) * 128 + o];
    g_Wh[idx] = __float2half_rn(v);
}

// ---- main GEMM --------------------------------------------------------------

__global__ void __launch_bounds__(256, 2)
mgc_kernel(const float* __restrict__ X, const float* __restrict__ bias,
           float* __restrict__ out) {
    extern __shared__ char smem[];
    const uint32_t sb  = smem_u32(smem);
    const int tid = threadIdx.x;
    const int lid = tid & 31;
    const int wid = tid >> 5;
    const int wm  = wid >> 1;          // 0..3  (32-row slices)
    const int wn  = wid & 1;           // 0..1  (64-col slices)
    const int m0  = blockIdx.x * BLOCK_M;

    if (tid < 128)
        reinterpret_cast<float*>(smem)[tid] = bias[tid];

    const int arow = lid >> 2;                 // fragment row within 8
    const int ac2  = (lid & 3) * 2;            // fragment col pair base
    const int bnrow = wn * 64 + (lid & 7);     // ldmatrix B row (+= nt*8)
    const int bcsel = (lid >> 3) & 1;          // B k-chunk selector within k16

    float acc[2][8][4];
    #pragma unroll
    for (int mt = 0; mt < 2; mt++)
        #pragma unroll
        for (int nt = 0; nt < 8; nt++)
            #pragma unroll
            for (int v = 0; v < 4; v++) acc[mt][nt][v] = 0.f;

    // prologue: fill ring
    #pragma unroll
    for (int p = 0; p < NSTAGES; p++) {
        issue_stage(X, sb, p, p, m0, tid);
        asm volatile("cp.async.commit_group;" ::: "memory");
    }

    const int NITER = KTOT / 32;   // 32
    for (int t = 0; t < NITER; t++) {
        const int slot = (t & (NSTAGES - 1));
        asm volatile("cp.async.wait_group %0;" :: "n"(NSTAGES - 1) : "memory");
        __syncthreads();

        const uint32_t aB = sb + SMEM_STAGE0 + slot * STAGE_BYTES;
        const uint32_t bB = aB + A_BYTES;

        #pragma unroll
        for (int j = 0; j < 2; j++) {            // two k16 steps
            // B fragments: 8 n-tiles, ldmatrix.x2 covers k16
            uint32_t bf[8][2];
            #pragma unroll
            for (int nt = 0; nt < 8; nt++) {
                int n = bnrow + nt * 8;
                int c = 2 * j + bcsel;
                uint32_t addr = bB + (uint32_t)(n * 64 + ((c ^ ((n >> 1) & 3)) << 4));
                ldsm_x2(bf[nt], addr);
            }
            // A fragments: f32 smem -> f16 regs
            uint32_t af[2][4];
            #pragma unroll
            for (int mt = 0; mt < 2; mt++) {
                int R  = wm * 32 + mt * 16;
                int cl = j * 16 + ac2;
                af[mt][0] = a_pair_f16(aB, R + arow,     cl);
                af[mt][1] = a_pair_f16(aB, R + arow + 8, cl);
                af[mt][2] = a_pair_f16(aB, R + arow,     cl + 8);
                af[mt][3] = a_pair_f16(aB, R + arow + 8, cl + 8);
            }
            #pragma unroll
            for (int mt = 0; mt < 2; mt++)
                #pragma unroll
                for (int nt = 0; nt < 8; nt++)
                    mma_f16(acc[mt][nt], af[mt], bf[nt][0], bf[nt][1]);
        }

        __syncthreads();
        if (t + NSTAGES < NITER)
            issue_stage(X, sb, slot, t + NSTAGES, m0, tid);
        asm volatile("cp.async.commit_group;" ::: "memory");
    }

    // ---- epilogue: acc + bias -> out ----------------------------------------
    const float* bs = reinterpret_cast<const float*>(smem);
    const int tig = lid & 3;
    const int g   = lid >> 2;

    float2 bv[8];
    #pragma unroll
    for (int nt = 0; nt < 8; nt++) {
        int c = wn * 64 + nt * 8 + 2 * tig;
        bv[nt].x = bs[c];
        bv[nt].y = bs[c + 1];
    }

    #pragma unroll
    for (int mt = 0; mt < 2; mt++) {
        int mrow = m0 + wm * 32 + mt * 16 + g;
        #pragma unroll
        for (int half = 0; half < 2; half++) {       // rows g and g+8
            int m = mrow + half * 8;
            if (m < NROWS) {
                float* po = out + (size_t)m * 128 + wn * 64;
                #pragma unroll
                for (int nt = 0; nt < 8; nt++) {
                    float2 v;
                    v.x = acc[mt][nt][2 * half + 0] + bv[nt].x;
                    v.y = acc[mt][nt][2 * half + 1] + bv[nt].y;
                    *reinterpret_cast<float2*>(po + nt * 8 + 2 * tig) = v;
                }
            }
        }
    }
}

// ---- launch -----------------------------------------------------------------

extern "C" void kernel_launch(void* const* d_in, const int* in_sizes, int n_in,
                              void* d_out, int out_size) {
    const float* X    = (const float*)d_in[0];   // (8, 200000, 128) f32
    const float* W    = (const float*)d_in[1];   // (8, 128, 128)    f32
    const float* attn = (const float*)d_in[2];   // (8,)             f32
    const float* bias = (const float*)d_in[3];   // (128,)           f32
    float* out = (float*)d_out;                  // (200000, 128)    f32

    cudaFuncSetAttribute(mgc_kernel, cudaFuncAttributeMaxDynamicSharedMemorySize,
                         SMEM_TOTAL);

    prep_kernel<<<(128 * KTOT + 255) / 256, 256>>>(W, attn);

    int grid = (NROWS + BLOCK_M - 1) / BLOCK_M;   // 1563
    mgc_kernel<<<grid, 256, SMEM_TOTAL>>>(X, bias, out);
}